// round 16
// baseline (speedup 1.0000x reference)
#include <cuda_runtime.h>
#include <cuda_bf16.h>
#include <cstdint>

// Problem: cam (32,4,512,512) f32 -> out[32,4] = mean of top 5243 per row
#define ROWS      128
#define N_PER_ROW (512*512)     // 262144
#define K_SEL     5243
#define SPLIT     16            // stream CTAs per row
#define NT1       256
#define NW1       (NT1/32)      // 8
#define WCAP      128           // per-warp cap: mean ~46.6, sd ~6.8 -> +12 sigma
#define PCAP      (NW1*WCAP)    // 1024 floats per part (16B-aligned)
#define NT2       512
#define NW2       (NT2/32)      // 16
#define CCAP      8192          // smem candidate cap (cc ~5963 + pad)
#define NHPAD     2048          // 1536 fine buckets + overflow, padded
#define LCAP      512           // in-bucket list cap (expected ~40)
#define BITS_T    0x40000000u   // raw bits of 2.0f (threshold)
#define D_RANGE   (1536u << 14) // fine-bucket key range [2.0, 16)
#define OVFL      1536          // overflow bucket index (v >= 16)

// ---- static device scratch ----
__device__ __align__(16) float g_cand[(size_t)ROWS * SPLIT * PCAP];
__device__ int g_pcnt[ROWS * SPLIT];

__device__ __forceinline__ unsigned mono(unsigned x) {
    return (x & 0x80000000u) ? ~x : (x | 0x80000000u);
}
__device__ __forceinline__ float unmono(unsigned k) {
    unsigned b = (k & 0x80000000u) ? (k ^ 0x80000000u) : ~k;
    return __uint_as_float(b);
}

// ---- Kernel 1: stream 128MB; per-warp atomic-free compaction (proven 26us) ----
__global__ void __launch_bounds__(NT1) toptk_stream(const float* __restrict__ cam) {
    __shared__ float s_stage[NW1 * WCAP];
    __shared__ int   s_wcnt[NW1];

    const int bid  = blockIdx.x;
    const int row  = bid / SPLIT;
    const int part = bid % SPLIT;
    const int t    = threadIdx.x;
    const int wid  = t >> 5;
    const int lane = t & 31;
    const unsigned lmask_lt = (1u << lane) - 1u;

    const float4* src = (const float4*)(cam + (size_t)row * N_PER_ROW)
                        + (size_t)part * (N_PER_ROW / 4 / SPLIT);   // 4096 float4

    int wcnt = 0;  // identical in every lane of the warp
    float4 c0 = __ldcs(&src[t]),       c1 = __ldcs(&src[t + 256]),
           c2 = __ldcs(&src[t + 512]), c3 = __ldcs(&src[t + 768]);

    #pragma unroll 1
    for (int it = 0; it < 4; it++) {
        float4 n0 = c0, n1 = c1, n2 = c2, n3 = c3;
        if (it < 3) {
            int b = (it + 1) * 1024 + t;
            n0 = __ldcs(&src[b]);       n1 = __ldcs(&src[b + 256]);
            n2 = __ldcs(&src[b + 512]); n3 = __ldcs(&src[b + 768]);
        }
        float a[16] = {c0.x, c0.y, c0.z, c0.w, c1.x, c1.y, c1.z, c1.w,
                       c2.x, c2.y, c2.z, c2.w, c3.x, c3.y, c3.z, c3.w};
        #pragma unroll
        for (int j = 0; j < 16; j++) {
            float v = a[j];
            bool p = ((int)__float_as_uint(v) >= (int)BITS_T);  // positive v >= 2.0
            unsigned m = __ballot_sync(0xffffffffu, p);
            if (p) {
                int pos = wcnt + __popc(m & lmask_lt);
                if (pos < WCAP) s_stage[wid * WCAP + pos] = v;
            }
            wcnt += __popc(m);
        }
        c0 = n0; c1 = n1; c2 = n2; c3 = n3;
    }

    if (lane == 0) s_wcnt[wid] = wcnt;
    __syncthreads();

    int tot = 0, off = 0; bool bad = false;
    #pragma unroll
    for (int w = 0; w < NW1; w++) {
        int c = s_wcnt[w];
        if (c > WCAP) bad = true;
        int cl = c < WCAP ? c : WCAP;
        if (w < wid) off += cl;
        tot += cl;
    }
    int mycnt = s_wcnt[wid]; if (mycnt > WCAP) mycnt = WCAP;
    float* dst = g_cand + (size_t)bid * PCAP + off;
    for (int i = lane; i < mycnt; i += 32) dst[i] = s_stage[wid * WCAP + i];
    if (t == 0) g_pcnt[bid] = bad ? -1 : tot;
    // No explicit PDL trigger: implicit trigger at kernel completion guarantees
    // the dependent kernel sees all of g_cand/g_pcnt.
}

// ---- helpers (block = NT2 = 512) ----
template<int NB>
__device__ __forceinline__ void hclear(unsigned* cnt) {
    for (int i = threadIdx.x; i < NB; i += NT2) cnt[i] = 0u;
    __syncthreads();
}

// full-block count-only rank-select (for large NB); reset inside (race-safe)
template<int NB>
__device__ void sel_step(const unsigned* cnt, int r, int& B, unsigned& above_out,
                         unsigned* s_wtot, unsigned* s_wsuf,
                         int* sh_selb, unsigned* sh_above) {
    const int t = threadIdx.x, lane = t & 31, wid = t >> 5;
    constexpr int PB = (NB + NT2 - 1) / NT2;
    __syncthreads();
    if (t == 0) { *sh_selb = -1; *sh_above = 0u; }
    unsigned p = 0;
    #pragma unroll
    for (int i = 0; i < PB; i++) {
        int b = t * PB + i;
        if (b < NB) p += cnt[b];
    }
    unsigned incl = p;
    #pragma unroll
    for (int d = 1; d < 32; d <<= 1) {
        unsigned o = __shfl_down_sync(0xffffffffu, incl, d);
        if (lane + d < 32) incl += o;
    }
    if (lane == 0) s_wtot[wid] = incl;
    __syncthreads();
    if (wid == 0) {
        unsigned v = (lane < NW2) ? s_wtot[lane] : 0u;
        unsigned wincl = v;
        #pragma unroll
        for (int d = 1; d < NW2; d <<= 1) {
            unsigned o = __shfl_down_sync(0xffffffffu, wincl, d);
            if (lane + d < 32) wincl += o;
        }
        if (lane < NW2) s_wsuf[lane] = wincl - v;
    }
    __syncthreads();
    unsigned above = s_wsuf[wid] + (incl - p);
    unsigned ur = (unsigned)r;
    #pragma unroll
    for (int i = PB - 1; i >= 0; i--) {
        int b = t * PB + i;
        unsigned c = (b < NB) ? cnt[b] : 0u;
        if (above < ur && ur <= above + c) { *sh_selb = b; *sh_above = above; }
        above += c;
    }
    __syncthreads();
    B = *sh_selb; above_out = *sh_above;
}

// 128-bucket rank-select done by warp 0 only: 2 block barriers total.
__device__ void sel128_warp(const unsigned* cnt, int r, int& B, unsigned& above_out,
                            int* sh_selb, unsigned* sh_above) {
    const int t = threadIdx.x, lane = t & 31;
    __syncthreads();   // hist pass complete; orders prior reads of sh_selb
    if (t < 32) {
        if (lane == 0) { *sh_selb = -1; *sh_above = 0u; }
        __syncwarp();
        int base = lane * 4;
        unsigned c0 = cnt[base], c1 = cnt[base + 1], c2 = cnt[base + 2], c3 = cnt[base + 3];
        unsigned p = c0 + c1 + c2 + c3;
        unsigned incl = p;
        #pragma unroll
        for (int d = 1; d < 32; d <<= 1) {
            unsigned o = __shfl_down_sync(0xffffffffu, incl, d);
            if (lane + d < 32) incl += o;
        }
        unsigned above = incl - p;
        unsigned ur = (unsigned)r;
        unsigned cs[4] = {c0, c1, c2, c3};
        #pragma unroll
        for (int i = 3; i >= 0; i--) {
            unsigned c = cs[i];
            if (above < ur && ur <= above + c) { *sh_selb = base + i; *sh_above = above; }
            above += c;
        }
    }
    __syncthreads();
    B = *sh_selb; above_out = *sh_above;
}

__device__ void block_reduce(float ls, unsigned lc, float* s_rs, unsigned* s_rc,
                             float& S, unsigned& C) {
    const int lane = threadIdx.x & 31, wid = threadIdx.x >> 5;
    #pragma unroll
    for (int d = 16; d > 0; d >>= 1) {
        ls += __shfl_down_sync(0xffffffffu, ls, d);
        lc += __shfl_down_sync(0xffffffffu, lc, d);
    }
    if (lane == 0) { s_rs[wid] = ls; s_rc[wid] = lc; }
    __syncthreads();
    if (wid == 0) {
        ls = (lane < NW2) ? s_rs[lane] : 0.f;
        lc = (lane < NW2) ? s_rc[lane] : 0u;
        #pragma unroll
        for (int d = 16; d > 0; d >>= 1) {
            ls += __shfl_down_sync(0xffffffffu, ls, d);
            lc += __shfl_down_sync(0xffffffffu, lc, d);
        }
    }
    S = ls; C = lc;   // valid on thread 0 only
}

// ---- Kernel 2: prologue overlaps stream tail under PDL; safe without PDL ----
__global__ void __launch_bounds__(NT2) toptk_final(const float* __restrict__ cam,
                                                   float* __restrict__ out) {
    extern __shared__ float s_cand[];     // CCAP floats (32KB dynamic)
    __shared__ unsigned s_cnt[NHPAD];     // 8KB
    __shared__ float    s_list[LCAP];     // 2KB
    __shared__ unsigned s_wtot[NW2];
    __shared__ unsigned s_wsuf[NW2];
    __shared__ int      s_selb;
    __shared__ unsigned s_above;
    __shared__ float    s_rs[NW2];
    __shared__ unsigned s_rc[NW2];
    __shared__ int      s_pc[SPLIT];
    __shared__ int      s_off4[SPLIT + 1];
    __shared__ int      s_n[SPLIT];
    __shared__ int      s_cc;
    __shared__ int      s_nl;

    const int row = blockIdx.x;
    const int t   = threadIdx.x;

    // ---- data-independent prologue (overlaps stream drain under PDL) ----
    for (int i = t; i < NHPAD; i += NT2) s_cnt[i] = 0u;
    if (t == 0) s_nl = 0;

    // ---- wait for primary completion; trivially satisfied if not PDL-launched
#if __CUDA_ARCH__ >= 900
    cudaGridDependencySynchronize();
#endif

    if (t < SPLIT) s_pc[t] = g_pcnt[row * SPLIT + t];
    __syncthreads();
    if (t == 0) {
        int off4 = 0, cc = 0, badf = 0;
        #pragma unroll
        for (int p = 0; p < SPLIT; p++) {
            int c = s_pc[p];
            if (c < 0 || c > PCAP) { badf = 1; c = 0; }
            s_n[p] = c;
            s_off4[p] = off4;
            off4 += (c + 3) >> 2;
            cc += c;
        }
        s_off4[SPLIT] = off4;
        s_cc = badf ? -1 : cc;
    }
    __syncthreads();
    const int cc = s_cc;
    const int cc_pad4 = s_off4[SPLIT];
    const int cc_pad  = cc_pad4 * 4;

    if (cc >= K_SEL && cc_pad <= CCAP) {
        // ---- FUSED gather + histogram (single pass over global candidates) ----
        const float4* gbase = (const float4*)g_cand;
        const int rowseg0 = row * SPLIT;
        for (int i = t; i < cc_pad4; i += NT2) {
            int p = 0;
            #pragma unroll
            for (int q = 1; q < SPLIT; q++) p += (i >= s_off4[q]);
            int j = i - s_off4[p];
            float4 v = gbase[(size_t)(rowseg0 + p) * (PCAP / 4) + j];
            int n = s_n[p];
            int lb = j * 4, b = i * 4;
            float vv[4] = {v.x, v.y, v.z, v.w};
            #pragma unroll
            for (int e = 0; e < 4; e++) {
                float val = (lb + e < n) ? vv[e] : 0.f;
                s_cand[b + e] = val;
                unsigned d = __float_as_uint(val) - BITS_T;
                if (d < D_RANGE)          atomicAdd(&s_cnt[d >> 14], 1u);
                else if (d < 0x40000000u) atomicAdd(&s_cnt[OVFL], 1u);  // v >= 16
            }
        }

        int B; unsigned above;
        sel_step<NHPAD>(s_cnt, K_SEL, B, above, s_wtot, s_wsuf, &s_selb, &s_above);

        if (B >= 0 && B != OVFL && s_cnt[B] <= (unsigned)LCAP) {
            const int r_in = K_SEL - (int)above;
            const unsigned hiKey = ((unsigned)(B + 1)) << 14;

            // ---- ONE combined pass over smem: sum above bucket + extract list
            float ls = 0.f; unsigned lc = 0u;
            for (int i = t; i < cc_pad; i += NT2) {
                float v = s_cand[i];
                unsigned d = __float_as_uint(v) - BITS_T;
                if (d >= hiKey && d < 0x40000000u) { ls += v; lc++; }
                else if ((d >> 14) == (unsigned)B) {
                    int pos = atomicAdd(&s_nl, 1);
                    if (pos < LCAP) s_list[pos] = v;
                }
            }
            float S_a; unsigned C_a;
            block_reduce(ls, lc, s_rs, s_rc, S_a, C_a);
            const int nl = s_nl;

            // ---- resolve exact key within bucket (tiny list) ----
            hclear<128>(s_cnt);
            for (int i = t; i < nl; i += NT2) {
                unsigned d = __float_as_uint(s_list[i]) - BITS_T;
                atomicAdd(&s_cnt[(d >> 7) & 127u], 1u);
            }
            int b1; sel128_warp(s_cnt, r_in, b1, above, &s_selb, &s_above);
            int r2 = r_in - (int)above;
            unsigned pref = (((unsigned)B) << 7) | (unsigned)b1;

            hclear<128>(s_cnt);
            for (int i = t; i < nl; i += NT2) {
                unsigned d = __float_as_uint(s_list[i]) - BITS_T;
                if ((d >> 7) == pref) atomicAdd(&s_cnt[d & 127u], 1u);
            }
            int b0; sel128_warp(s_cnt, r2, b0, above, &s_selb, &s_above);

            float vt = __uint_as_float(BITS_T + ((pref << 7) | (unsigned)b0));

            float ls2 = 0.f; unsigned lc2 = 0u;
            for (int i = t; i < nl; i += NT2) {
                float v = s_list[i];
                if (v > vt) { ls2 += v; lc2++; }
            }
            float S_l; unsigned C_l;
            block_reduce(ls2, lc2, s_rs, s_rc, S_l, C_l);
            if (t == 0) {
                int ties = K_SEL - (int)C_a - (int)C_l;
                out[row] = (S_a + S_l + (float)ties * vt) / (float)K_SEL;
            }
            return;
        }
        __syncthreads();
        // degenerate bucket -> exact full-row below
    }

    // ---- exact full-row fallback: 11/11/10-bit count radix over mono keys ----
    {
        const float* rowp = cam + (size_t)row * N_PER_ROW;
        int r = K_SEL; unsigned above;

        hclear<NHPAD>(s_cnt);
        for (int i = t; i < N_PER_ROW; i += NT2)
            atomicAdd(&s_cnt[mono(__float_as_uint(rowp[i])) >> 21], 1u);
        int B0; sel_step<NHPAD>(s_cnt, r, B0, above, s_wtot, s_wsuf, &s_selb, &s_above);
        r -= (int)above;
        unsigned pref = ((unsigned)B0) << 21;

        hclear<NHPAD>(s_cnt);
        for (int i = t; i < N_PER_ROW; i += NT2) {
            unsigned k = mono(__float_as_uint(rowp[i]));
            if ((k >> 21) == (unsigned)B0) atomicAdd(&s_cnt[(k >> 10) & 2047u], 1u);
        }
        int d1; sel_step<NHPAD>(s_cnt, r, d1, above, s_wtot, s_wsuf, &s_selb, &s_above);
        r -= (int)above;
        pref |= ((unsigned)d1) << 10;

        hclear<1024>(s_cnt);
        for (int i = t; i < N_PER_ROW; i += NT2) {
            unsigned k = mono(__float_as_uint(rowp[i]));
            if ((k & 0xFFFFFC00u) == pref) atomicAdd(&s_cnt[k & 1023u], 1u);
        }
        int d0; sel_step<1024>(s_cnt, r, d0, above, s_wtot, s_wsuf, &s_selb, &s_above);
        unsigned kt = pref | (unsigned)d0;

        float ls = 0.f; unsigned lc = 0u;
        for (int i = t; i < N_PER_ROW; i += NT2) {
            float v = rowp[i];
            if (mono(__float_as_uint(v)) > kt) { ls += v; lc++; }
        }
        float S; unsigned C;
        block_reduce(ls, lc, s_rs, s_rc, S, C);
        if (t == 0) out[row] = (S + (float)(K_SEL - (int)C) * unmono(kt)) / (float)K_SEL;
    }
}

extern "C" void kernel_launch(void* const* d_in, const int* in_sizes, int n_in,
                              void* d_out, int out_size) {
    const float* cam = (const float*)d_in[0];
    float* out = (float*)d_out;
    cudaFuncSetAttribute(toptk_final, cudaFuncAttributeMaxDynamicSharedMemorySize,
                         CCAP * sizeof(float));

    toptk_stream<<<ROWS * SPLIT, NT1>>>(cam);

    // PDL attempt: secondary may begin (prologue only) while primary drains;
    // cudaGridDependencySynchronize() gates all reads of primary output.
    cudaLaunchConfig_t cfg = {};
    cfg.gridDim = dim3(ROWS, 1, 1);
    cfg.blockDim = dim3(NT2, 1, 1);
    cfg.dynamicSmemBytes = CCAP * sizeof(float);
    cfg.stream = 0;   // same (legacy default) stream as the <<<>>> launch above
    cudaLaunchAttribute attrs[1];
    attrs[0].id = cudaLaunchAttributeProgrammaticStreamSerialization;
    attrs[0].val.programmaticStreamSerializationAllowed = 1;
    cfg.attrs = attrs;
    cfg.numAttrs = 1;
    cudaError_t e = cudaLaunchKernelEx(&cfg, toptk_final, cam, out);
    if (e != cudaSuccess) {
        // Deterministic fallback: plain stream-ordered launch (38.9us baseline).
        // cudaGridDependencySynchronize is trivially satisfied in this mode.
        toptk_final<<<ROWS, NT2, CCAP * sizeof(float)>>>(cam, out);
    }
}

// round 17
// speedup vs baseline: 1.0546x; 1.0546x over previous
#include <cuda_runtime.h>
#include <cuda_bf16.h>
#include <cstdint>

// Problem: cam (32,4,512,512) f32 -> out[32,4] = mean of top 5243 per row
#define ROWS      128
#define N_PER_ROW (512*512)     // 262144
#define K_SEL     5243
#define SPLIT     32            // stream CTAs per row
#define NT1       256
#define NW1       (NT1/32)      // 8
#define WCAP      96            // per-warp cap: mean ~23.3, sd ~4.8 -> +15 sigma
#define PCAP      (NW1*WCAP)    // 768 floats per part (16B-aligned)
#define NT2       512
#define NW2       (NT2/32)      // 16
#define CCAP      8192          // smem candidate cap (cc ~5963 + pad)
#define NHPAD     2048          // 1536 fine buckets + overflow, padded
#define LCAP      512           // in-bucket list cap (expected ~40)
#define BITS_T    0x40000000u   // raw bits of 2.0f (threshold)
#define D_RANGE   (1536u << 14) // fine-bucket key range [2.0, 16)
#define OVFL      1536          // overflow bucket index (v >= 16)

// ---- static device scratch ----
__device__ __align__(16) float g_cand[(size_t)ROWS * SPLIT * PCAP];
__device__ int g_pcnt[ROWS * SPLIT];

__device__ __forceinline__ unsigned mono(unsigned x) {
    return (x & 0x80000000u) ? ~x : (x | 0x80000000u);
}
__device__ __forceinline__ float unmono(unsigned k) {
    unsigned b = (k & 0x80000000u) ? (k ^ 0x80000000u) : ~k;
    return __uint_as_float(b);
}

// ---- Kernel 1: stream 128MB; 8 LDG.128 in flight, loop-free body ----
__global__ void __launch_bounds__(NT1) toptk_stream(const float* __restrict__ cam) {
    __shared__ float s_stage[NW1 * WCAP];
    __shared__ int   s_wcnt[NW1];

    const int bid  = blockIdx.x;
    const int row  = bid / SPLIT;
    const int part = bid % SPLIT;
    const int t    = threadIdx.x;
    const int wid  = t >> 5;
    const int lane = t & 31;
    const unsigned lmask_lt = (1u << lane) - 1u;

    const float4* src = (const float4*)(cam + (size_t)row * N_PER_ROW)
                        + (size_t)part * (N_PER_ROW / 4 / SPLIT);   // 2048 float4

    // 8 independent 16B loads issued back-to-back: 128B in flight per thread
    float4 c0 = __ldcs(&src[t]),        c1 = __ldcs(&src[t + 256]);
    float4 c2 = __ldcs(&src[t + 512]),  c3 = __ldcs(&src[t + 768]);
    float4 c4 = __ldcs(&src[t + 1024]), c5 = __ldcs(&src[t + 1280]);
    float4 c6 = __ldcs(&src[t + 1536]), c7 = __ldcs(&src[t + 1792]);

    int wcnt = 0;  // identical in every lane of the warp
    float a[32] = {c0.x, c0.y, c0.z, c0.w, c1.x, c1.y, c1.z, c1.w,
                   c2.x, c2.y, c2.z, c2.w, c3.x, c3.y, c3.z, c3.w,
                   c4.x, c4.y, c4.z, c4.w, c5.x, c5.y, c5.z, c5.w,
                   c6.x, c6.y, c6.z, c6.w, c7.x, c7.y, c7.z, c7.w};
    #pragma unroll
    for (int j = 0; j < 32; j++) {
        float v = a[j];
        bool p = ((int)__float_as_uint(v) >= (int)BITS_T);  // positive v >= 2.0
        unsigned m = __ballot_sync(0xffffffffu, p);
        if (p) {
            int pos = wcnt + __popc(m & lmask_lt);
            if (pos < WCAP) s_stage[wid * WCAP + pos] = v;
        }
        wcnt += __popc(m);
    }

    if (lane == 0) s_wcnt[wid] = wcnt;
    __syncthreads();

    int tot = 0, off = 0; bool bad = false;
    #pragma unroll
    for (int w = 0; w < NW1; w++) {
        int c = s_wcnt[w];
        if (c > WCAP) bad = true;
        int cl = c < WCAP ? c : WCAP;
        if (w < wid) off += cl;
        tot += cl;
    }
    int mycnt = s_wcnt[wid]; if (mycnt > WCAP) mycnt = WCAP;
    float* dst = g_cand + (size_t)bid * PCAP + off;
    for (int i = lane; i < mycnt; i += 32) dst[i] = s_stage[wid * WCAP + i];
    if (t == 0) g_pcnt[bid] = bad ? -1 : tot;
}

// ---- helpers (block = NT2 = 512) ----
template<int NB>
__device__ __forceinline__ void hclear(unsigned* cnt) {
    for (int i = threadIdx.x; i < NB; i += NT2) cnt[i] = 0u;
    __syncthreads();
}

// full-block count-only rank-select (large NB); reset inside (race-safe)
template<int NB>
__device__ void sel_step(const unsigned* cnt, int r, int& B, unsigned& above_out,
                         unsigned* s_wtot, unsigned* s_wsuf,
                         int* sh_selb, unsigned* sh_above) {
    const int t = threadIdx.x, lane = t & 31, wid = t >> 5;
    constexpr int PB = (NB + NT2 - 1) / NT2;
    __syncthreads();
    if (t == 0) { *sh_selb = -1; *sh_above = 0u; }
    unsigned p = 0;
    #pragma unroll
    for (int i = 0; i < PB; i++) {
        int b = t * PB + i;
        if (b < NB) p += cnt[b];
    }
    unsigned incl = p;
    #pragma unroll
    for (int d = 1; d < 32; d <<= 1) {
        unsigned o = __shfl_down_sync(0xffffffffu, incl, d);
        if (lane + d < 32) incl += o;
    }
    if (lane == 0) s_wtot[wid] = incl;
    __syncthreads();
    if (wid == 0) {
        unsigned v = (lane < NW2) ? s_wtot[lane] : 0u;
        unsigned wincl = v;
        #pragma unroll
        for (int d = 1; d < NW2; d <<= 1) {
            unsigned o = __shfl_down_sync(0xffffffffu, wincl, d);
            if (lane + d < 32) wincl += o;
        }
        if (lane < NW2) s_wsuf[lane] = wincl - v;
    }
    __syncthreads();
    unsigned above = s_wsuf[wid] + (incl - p);
    unsigned ur = (unsigned)r;
    #pragma unroll
    for (int i = PB - 1; i >= 0; i--) {
        int b = t * PB + i;
        unsigned c = (b < NB) ? cnt[b] : 0u;
        if (above < ur && ur <= above + c) { *sh_selb = b; *sh_above = above; }
        above += c;
    }
    __syncthreads();
    B = *sh_selb; above_out = *sh_above;
}

// 128-bucket rank-select by warp 0 only: 2 block barriers total.
__device__ void sel128_warp(const unsigned* cnt, int r, int& B, unsigned& above_out,
                            int* sh_selb, unsigned* sh_above) {
    const int t = threadIdx.x, lane = t & 31;
    __syncthreads();
    if (t < 32) {
        if (lane == 0) { *sh_selb = -1; *sh_above = 0u; }
        __syncwarp();
        int base = lane * 4;
        unsigned c0 = cnt[base], c1 = cnt[base + 1], c2 = cnt[base + 2], c3 = cnt[base + 3];
        unsigned p = c0 + c1 + c2 + c3;
        unsigned incl = p;
        #pragma unroll
        for (int d = 1; d < 32; d <<= 1) {
            unsigned o = __shfl_down_sync(0xffffffffu, incl, d);
            if (lane + d < 32) incl += o;
        }
        unsigned above = incl - p;
        unsigned ur = (unsigned)r;
        unsigned cs[4] = {c0, c1, c2, c3};
        #pragma unroll
        for (int i = 3; i >= 0; i--) {
            unsigned c = cs[i];
            if (above < ur && ur <= above + c) { *sh_selb = base + i; *sh_above = above; }
            above += c;
        }
    }
    __syncthreads();
    B = *sh_selb; above_out = *sh_above;
}

__device__ void block_reduce(float ls, unsigned lc, float* s_rs, unsigned* s_rc,
                             float& S, unsigned& C) {
    const int lane = threadIdx.x & 31, wid = threadIdx.x >> 5;
    #pragma unroll
    for (int d = 16; d > 0; d >>= 1) {
        ls += __shfl_down_sync(0xffffffffu, ls, d);
        lc += __shfl_down_sync(0xffffffffu, lc, d);
    }
    if (lane == 0) { s_rs[wid] = ls; s_rc[wid] = lc; }
    __syncthreads();
    if (wid == 0) {
        ls = (lane < NW2) ? s_rs[lane] : 0.f;
        lc = (lane < NW2) ? s_rc[lane] : 0u;
        #pragma unroll
        for (int d = 16; d > 0; d >>= 1) {
            ls += __shfl_down_sync(0xffffffffu, ls, d);
            lc += __shfl_down_sync(0xffffffffu, lc, d);
        }
    }
    S = ls; C = lc;   // valid on thread 0 only
}

// ---- Kernel 2: segid-table gather+hist -> sel -> combined pass -> resolve ----
__global__ void __launch_bounds__(NT2) toptk_final(const float* __restrict__ cam,
                                                   float* __restrict__ out) {
    extern __shared__ float s_cand[];        // CCAP floats (32KB dynamic)
    __shared__ unsigned      s_cnt[NHPAD];   // 8KB
    __shared__ float         s_list[LCAP];   // 2KB
    __shared__ unsigned char s_segid[CCAP / 4];  // 2KB: float4-index -> segment
    __shared__ unsigned s_wtot[NW2];
    __shared__ unsigned s_wsuf[NW2];
    __shared__ int      s_selb;
    __shared__ unsigned s_above;
    __shared__ float    s_rs[NW2];
    __shared__ unsigned s_rc[NW2];
    __shared__ int      s_pc[SPLIT];
    __shared__ int      s_off4[SPLIT + 1];
    __shared__ int      s_n[SPLIT];
    __shared__ int      s_cc;
    __shared__ int      s_nl;

    const int row = blockIdx.x;
    const int t   = threadIdx.x;

    if (t < SPLIT) s_pc[t] = g_pcnt[row * SPLIT + t];
    for (int i = t; i < NHPAD; i += NT2) s_cnt[i] = 0u;
    __syncthreads();
    if (t == 0) {
        int off4 = 0, cc = 0, badf = 0;
        #pragma unroll
        for (int p = 0; p < SPLIT; p++) {
            int c = s_pc[p];
            if (c < 0 || c > PCAP) { badf = 1; c = 0; }
            s_n[p] = c;
            s_off4[p] = off4;
            off4 += (c + 3) >> 2;
            cc += c;
        }
        s_off4[SPLIT] = off4;
        s_cc = badf ? -1 : cc;
        s_nl = 0;
    }
    __syncthreads();
    const int cc = s_cc;
    const int cc_pad4 = s_off4[SPLIT];
    const int cc_pad  = cc_pad4 * 4;

    if (cc >= K_SEL && cc_pad <= CCAP) {
        // build segment-id lookup (each of SPLIT threads fills its range)
        if (t < SPLIT) {
            int s = s_off4[t], e = s_off4[t + 1];
            for (int i = s; i < e; i++) s_segid[i] = (unsigned char)t;
        }
        __syncthreads();

        // ---- FUSED gather + histogram (single pass over global candidates) ----
        const float4* gbase = (const float4*)g_cand;
        const int rowseg0 = row * SPLIT;
        for (int i = t; i < cc_pad4; i += NT2) {
            int p = s_segid[i];
            int j = i - s_off4[p];
            float4 v = gbase[(size_t)(rowseg0 + p) * (PCAP / 4) + j];
            int n = s_n[p];
            int lb = j * 4, b = i * 4;
            float vv[4] = {v.x, v.y, v.z, v.w};
            #pragma unroll
            for (int e = 0; e < 4; e++) {
                float val = (lb + e < n) ? vv[e] : 0.f;
                s_cand[b + e] = val;
                unsigned d = __float_as_uint(val) - BITS_T;
                if (d < D_RANGE)          atomicAdd(&s_cnt[d >> 14], 1u);
                else if (d < 0x40000000u) atomicAdd(&s_cnt[OVFL], 1u);  // v >= 16
                // sentinel 0 wraps out of range -> skipped
            }
        }

        int B; unsigned above;
        sel_step<NHPAD>(s_cnt, K_SEL, B, above, s_wtot, s_wsuf, &s_selb, &s_above);

        if (B >= 0 && B != OVFL && s_cnt[B] <= (unsigned)LCAP) {
            const int r_in = K_SEL - (int)above;
            const unsigned hiKey = ((unsigned)(B + 1)) << 14;

            // ---- ONE combined pass over smem: sum above bucket + extract list
            float ls = 0.f; unsigned lc = 0u;
            for (int i = t; i < cc_pad; i += NT2) {
                float v = s_cand[i];
                unsigned d = __float_as_uint(v) - BITS_T;
                if (d >= hiKey && d < 0x40000000u) { ls += v; lc++; }
                else if ((d >> 14) == (unsigned)B) {
                    int pos = atomicAdd(&s_nl, 1);
                    if (pos < LCAP) s_list[pos] = v;
                }
            }
            float S_a; unsigned C_a;
            block_reduce(ls, lc, s_rs, s_rc, S_a, C_a);
            const int nl = s_nl;

            // ---- resolve exact key within bucket (tiny list, warp sels) ----
            hclear<128>(s_cnt);
            for (int i = t; i < nl; i += NT2) {
                unsigned d = __float_as_uint(s_list[i]) - BITS_T;
                atomicAdd(&s_cnt[(d >> 7) & 127u], 1u);
            }
            int b1; sel128_warp(s_cnt, r_in, b1, above, &s_selb, &s_above);
            int r2 = r_in - (int)above;
            unsigned pref = (((unsigned)B) << 7) | (unsigned)b1;

            hclear<128>(s_cnt);
            for (int i = t; i < nl; i += NT2) {
                unsigned d = __float_as_uint(s_list[i]) - BITS_T;
                if ((d >> 7) == pref) atomicAdd(&s_cnt[d & 127u], 1u);
            }
            int b0; sel128_warp(s_cnt, r2, b0, above, &s_selb, &s_above);

            float vt = __uint_as_float(BITS_T + ((pref << 7) | (unsigned)b0));

            float ls2 = 0.f; unsigned lc2 = 0u;
            for (int i = t; i < nl; i += NT2) {
                float v = s_list[i];
                if (v > vt) { ls2 += v; lc2++; }
            }
            float S_l; unsigned C_l;
            block_reduce(ls2, lc2, s_rs, s_rc, S_l, C_l);
            if (t == 0) {
                int ties = K_SEL - (int)C_a - (int)C_l;
                out[row] = (S_a + S_l + (float)ties * vt) / (float)K_SEL;
            }
            return;
        }
        __syncthreads();
        // degenerate bucket -> exact full-row below
    }

    // ---- exact full-row fallback: 11/11/10-bit count radix over mono keys ----
    {
        const float* rowp = cam + (size_t)row * N_PER_ROW;
        int r = K_SEL; unsigned above;

        hclear<NHPAD>(s_cnt);
        for (int i = t; i < N_PER_ROW; i += NT2)
            atomicAdd(&s_cnt[mono(__float_as_uint(rowp[i])) >> 21], 1u);
        int B0; sel_step<NHPAD>(s_cnt, r, B0, above, s_wtot, s_wsuf, &s_selb, &s_above);
        r -= (int)above;
        unsigned pref = ((unsigned)B0) << 21;

        hclear<NHPAD>(s_cnt);
        for (int i = t; i < N_PER_ROW; i += NT2) {
            unsigned k = mono(__float_as_uint(rowp[i]));
            if ((k >> 21) == (unsigned)B0) atomicAdd(&s_cnt[(k >> 10) & 2047u], 1u);
        }
        int d1; sel_step<NHPAD>(s_cnt, r, d1, above, s_wtot, s_wsuf, &s_selb, &s_above);
        r -= (int)above;
        pref |= ((unsigned)d1) << 10;

        hclear<1024>(s_cnt);
        for (int i = t; i < N_PER_ROW; i += NT2) {
            unsigned k = mono(__float_as_uint(rowp[i]));
            if ((k & 0xFFFFFC00u) == pref) atomicAdd(&s_cnt[k & 1023u], 1u);
        }
        int d0; sel_step<1024>(s_cnt, r, d0, above, s_wtot, s_wsuf, &s_selb, &s_above);
        unsigned kt = pref | (unsigned)d0;

        float ls = 0.f; unsigned lc = 0u;
        for (int i = t; i < N_PER_ROW; i += NT2) {
            float v = rowp[i];
            if (mono(__float_as_uint(v)) > kt) { ls += v; lc++; }
        }
        float S; unsigned C;
        block_reduce(ls, lc, s_rs, s_rc, S, C);
        if (t == 0) out[row] = (S + (float)(K_SEL - (int)C) * unmono(kt)) / (float)K_SEL;
    }
}

extern "C" void kernel_launch(void* const* d_in, const int* in_sizes, int n_in,
                              void* d_out, int out_size) {
    const float* cam = (const float*)d_in[0];
    float* out = (float*)d_out;
    cudaFuncSetAttribute(toptk_final, cudaFuncAttributeMaxDynamicSharedMemorySize,
                         CCAP * sizeof(float));
    toptk_stream<<<ROWS * SPLIT, NT1>>>(cam);
    toptk_final<<<ROWS, NT2, CCAP * sizeof(float)>>>(cam, out);
}